// round 11
// baseline (speedup 1.0000x reference)
#include <cuda_runtime.h>
#include <cuda_fp16.h>
#include <string.h>

// LearnableConvCensus: depthwise 3x3 conv (multiplier 8) -> sigmoid -> mean over 8.
// B=4, C=64, H=W=256, pad=1.
//
// sigmoid(z) = 0.5 + 0.5*tanh(z/2); fold 0.5*temperature[c] into pre-scaled
// weights/bias. out = 0.5 + (sum_m tanh_m) / 16.
//
// R11: R9 skeleton + f16x2 epilogue: tanh.approx.f16x2 computes 2 tanh per
// MUFU instruction (theory: MUFU is the binding pipe at rt16 per tanh.f32;
// the 66% fma plateau = 328/496 MUFU-bound span). Sum via add.rn.f16x2 tree.

#define B_ 4
#define C_ 64
#define H_ 256
#define W_ 256
#define R_ 32                 // output rows per block
#define NROWS (R_ + 2)        // tile rows incl. halo
#define SROW 264              // smem row stride in floats

typedef unsigned long long ull;

__device__ __forceinline__ ull pack2(float lo, float hi) {
    ull r;
    asm("mov.b64 %0, {%1, %2};" : "=l"(r) : "f"(lo), "f"(hi));
    return r;
}
__device__ __forceinline__ ull dup2(float v) {
    ull r;
    asm("mov.b64 %0, {%1, %1};" : "=l"(r) : "f"(v));
    return r;
}
__device__ __forceinline__ void fma2(ull& acc, ull a, ull b) {
    asm("fma.rn.f32x2 %0, %1, %2, %0;" : "+l"(acc) : "l"(a), "l"(b));
}
// f32x2 pair -> f16x2 -> tanh.approx.f16x2 (one MUFU inst for 2 values)
__device__ __forceinline__ unsigned tanh2_from_acc(ull acc) {
    float2 a;
    memcpy(&a, &acc, 8);
    unsigned h, t;
    asm("cvt.rn.f16x2.f32 %0, %1, %2;" : "=r"(h) : "f"(a.y), "f"(a.x));
    asm("tanh.approx.f16x2 %0, %1;" : "=r"(t) : "r"(h));
    return t;
}
__device__ __forceinline__ unsigned hadd2(unsigned a, unsigned b) {
    unsigned d;
    asm("add.rn.f16x2 %0, %1, %2;" : "=r"(d) : "r"(a), "r"(b));
    return d;
}

__global__ __launch_bounds__(128, 4)
void census_kernel(const float* __restrict__ x, const float* __restrict__ w,
                   const float* __restrict__ bias, const float* __restrict__ temp,
                   float* __restrict__ out) {
    __shared__ float      smem[NROWS * SROW];
    __shared__ ulonglong2 wsm2[9][2];   // [k][0]=(pair0,pair1), [k][1]=(pair2,pair3)
    __shared__ ull        bsm[4];

    const int bid   = blockIdx.x;
    const int strip = bid & 7;          // H_/R_ = 8 strips
    const int c     = (bid >> 3) & 63;
    const int b     = bid >> 9;
    const int h0    = strip * R_;
    const int tid   = threadIdx.x;

    const float* xp = x + ((size_t)(b * C_ + c) * H_) * W_;

    // ---- weight prep: w layout HWIO flattened w[(kh*3+kw)*512 + c*8 + m]
    if (tid < 40) {
        const float sc = 0.5f * __ldg(&temp[c]);
        if (tid < 36) {
            const int k = tid >> 2, p = tid & 3;
            const float w0 = __ldg(&w[k * 512 + (c << 3) + 2 * p])     * sc;
            const float w1 = __ldg(&w[k * 512 + (c << 3) + 2 * p + 1]) * sc;
            ((ull*)wsm2)[k * 4 + p] = pack2(w0, w1);
        } else {
            const int p = tid - 36;
            const float b0 = __ldg(&bias[(c << 3) + 2 * p])     * sc;
            const float b1 = __ldg(&bias[(c << 3) + 2 * p + 1]) * sc;
            bsm[p] = pack2(b0, b1);
        }
    }

    // ---- tile load: smem[r][4 + wcol] = x[h0 + r - 1][wcol]; cols 3 & 260 are
    // the zero conv padding (tiles span the full width).
    #pragma unroll
    for (int i = tid; i < NROWS * 64; i += 128) {
        const int r  = i >> 6;
        const int c4 = (i & 63) << 2;
        const int gh = h0 + r - 1;
        float4 v = make_float4(0.f, 0.f, 0.f, 0.f);
        if (gh >= 0 && gh < H_) v = *(const float4*)(xp + gh * W_ + c4);
        *(float4*)&smem[r * SROW + 4 + c4] = v;
    }
    for (int r = tid; r < NROWS; r += 128) {
        smem[r * SROW + 3]   = 0.f;
        smem[r * SROW + 260] = 0.f;
    }
    __syncthreads();

    const ull bp0 = bsm[0], bp1 = bsm[1], bp2 = bsm[2], bp3 = bsm[3];

    const int tx = tid & 63;   // 64 threads across width, 4 cols each
    const int ty = tid >> 6;   // 2 row-groups
    float* outp = out + (((size_t)(b * C_ + c) * H_) + h0) * W_ + (tx << 2);

    // conv of one output row into acc[p][j] (p = multiplier pair, j = column)
    auto conv = [&](int r, ull acc[4][4]) {
        #pragma unroll
        for (int j = 0; j < 4; j++) {
            acc[0][j] = bp0; acc[1][j] = bp1;
            acc[2][j] = bp2; acc[3][j] = bp3;
        }
        #pragma unroll
        for (int kh = 0; kh < 3; kh++) {
            const float* rowp = &smem[(r + kh) * SROW + (tx << 2)];
            const float  wm1 = rowp[3];
            const float4 f4  = *(const float4*)(rowp + 4);
            const float  wp4 = rowp[8];
            ull d[6];
            d[0] = dup2(wm1);
            d[1] = dup2(f4.x);
            d[2] = dup2(f4.y);
            d[3] = dup2(f4.z);
            d[4] = dup2(f4.w);
            d[5] = dup2(wp4);
            #pragma unroll
            for (int kw = 0; kw < 3; kw++) {
                const ulonglong2 w01 = wsm2[kh * 3 + kw][0];  // LDS.128
                const ulonglong2 w23 = wsm2[kh * 3 + kw][1];  // LDS.128
                #pragma unroll
                for (int j = 0; j < 4; j++) {
                    fma2(acc[0][j], d[j + kw], w01.x);
                    fma2(acc[1][j], d[j + kw], w01.y);
                    fma2(acc[2][j], d[j + kw], w23.x);
                    fma2(acc[3][j], d[j + kw], w23.y);
                }
            }
        }
    };

    // epilogue: per column j, 4 f16x2 tanh (8 values) -> add tree -> mean
    auto epi = [&](ull acc[4][4], int r) {
        float4 o;
        float* of = &o.x;
        #pragma unroll
        for (int j = 0; j < 4; j++) {
            const unsigned t0 = tanh2_from_acc(acc[0][j]);
            const unsigned t1 = tanh2_from_acc(acc[1][j]);
            const unsigned t2 = tanh2_from_acc(acc[2][j]);
            const unsigned t3 = tanh2_from_acc(acc[3][j]);
            const unsigned v  = hadd2(hadd2(t0, t1), hadd2(t2, t3));
            __half2 hv;
            memcpy(&hv, &v, 4);
            const float2 vf = __half22float2(hv);
            of[j] = fmaf(vf.x + vf.y, 0.0625f, 0.5f);
        }
        *(float4*)(outp + r * W_) = o;
    };

    // software pipeline: epi(row k) overlaps conv(row k+1)
    ull accA[4][4], accB[4][4];
    int r = ty;
    conv(r, accA);
    #pragma unroll 1
    for (int i = 0; i < 7; i++) {
        conv(r + 2, accB);
        epi(accA, r);
        conv(r + 4, accA);
        epi(accB, r + 2);
        r += 4;
    }
    conv(r + 2, accB);
    epi(accA, r);
    epi(accB, r + 2);
}

extern "C" void kernel_launch(void* const* d_in, const int* in_sizes, int n_in,
                              void* d_out, int out_size) {
    const float* x    = (const float*)d_in[0];
    const float* w    = (const float*)d_in[1];
    const float* bias = (const float*)d_in[2];
    const float* temp = (const float*)d_in[3];
    float* out = (float*)d_out;

    const int grid = B_ * C_ * (H_ / R_);   // 4*64*8 = 2048 blocks
    census_kernel<<<grid, 128>>>(x, w, bias, temp, out);
}